// round 15
// baseline (speedup 1.0000x reference)
#include <cuda_runtime.h>

#define NN   100000
#define NE   1600000
#define FIN  128
#define DIM  32
#define NC   40
#define CAP  128          // per-node bucket capacity (Poisson(16) -> P(>128) ~ 1e-80)
#define SAS  33           // smem activation stride: bank (t+k)%32 -> conflict-free

#define NB_EDGE ((NE + 255) / 256)     // 6250
#define NB_NODE ((NN + 255) / 256)     // 391

// ---------------- scratch (device globals — no runtime alloc) ----------------
__device__ __align__(16) float g_y   [(size_t)NN * DIM];
__device__ __align__(16) float g_aggY[(size_t)NN * DIM];
__device__ __align__(16) float g_z   [(size_t)NN * DIM];
__device__ __align__(16) float g_aggZ[(size_t)NN * DIM];
__device__ __align__(16) int   g_slot[(size_t)NN * CAP];   // bucketed CSC
__device__ __align__(16) int   g_deg [NN];
__device__ int g_is64;
__device__ __align__(16) float g_W2a [DIM * DIM];   // diag(s1) @ w2a
__device__ __align__(16) float g_c2a [DIM];         // (bn1_b - bn1_m*s1) @ w2a
__device__ __align__(16) float g_W2b [DIM * DIM];   // w2b @ diag(s2)
__device__ __align__(16) float g_bb2 [DIM];         // (b2b - bn2_m)*s2 + bn2_b

// ---------------- f32x2 packed-FMA helpers ----------------
typedef unsigned long long u64;
__device__ __forceinline__ void fma2(u64& d, u64 a, u64 b) {
    asm("fma.rn.f32x2 %0, %1, %2, %0;" : "+l"(d) : "l"(a), "l"(b));
}
__device__ __forceinline__ u64 bcast2(float a) {
    u64 v; asm("mov.b64 %0, {%1, %1};" : "=l"(v) : "f"(a)); return v;
}
__device__ __forceinline__ u64 pk2(float a, float b) {
    u64 v; asm("mov.b64 %0, {%1, %2};" : "=l"(v) : "f"(a), "f"(b)); return v;
}
__device__ __forceinline__ float2 up2(u64 v) {
    float2 f; asm("mov.b64 {%0, %1}, %2;" : "=f"(f.x), "=f"(f.y) : "l"(v)); return f;
}

// ---------------- init+setup: detect dtype, zero deg, fold BN (one launch) ----------------
__global__ void __launch_bounds__(1024) k_initsetup(
    const int* __restrict__ ei32,
    const float* __restrict__ w2a,
    const float* __restrict__ bn1_g, const float* __restrict__ bn1_b,
    const float* __restrict__ bn1_m, const float* __restrict__ bn1_v,
    const float* __restrict__ w2b,  const float* __restrict__ b2b,
    const float* __restrict__ bn2_g, const float* __restrict__ bn2_b,
    const float* __restrict__ bn2_m, const float* __restrict__ bn2_v) {
    int tid = threadIdx.x;
    if (blockIdx.x == 0) {
        if (tid == 0) {
            int all_zero = 1;
            for (int q = 1; q < 128; q += 2)
                if (ei32[q] != 0) { all_zero = 0; break; }
            g_is64 = all_zero;
        }
        int k = tid >> 5, j = tid & 31;
        float s1k = bn1_g[k] * rsqrtf(bn1_v[k] + 1e-5f);
        g_W2a[tid] = s1k * w2a[tid];
        float s2j = bn2_g[j] * rsqrtf(bn2_v[j] + 1e-5f);
        g_W2b[tid] = w2b[tid] * s2j;
        if (tid < DIM) {
            float c = 0.f;
            for (int kk = 0; kk < DIM; kk++) {
                float s = bn1_g[kk] * rsqrtf(bn1_v[kk] + 1e-5f);
                c += (bn1_b[kk] - bn1_m[kk] * s) * w2a[kk * DIM + tid];
            }
            g_c2a[tid] = c;
            float s2 = bn2_g[tid] * rsqrtf(bn2_v[tid] + 1e-5f);
            g_bb2[tid] = (b2b[tid] - bn2_m[tid]) * s2 + bn2_b[tid];
        }
    } else {
        int i = (blockIdx.x - 1) * 1024 + tid;
        if (i < NN) g_deg[i] = 0;
    }
}

// ---------------- fused: CSC fill (blocks [0,NB_EDGE)) + gemm1 (rest) ----------------
__global__ void __launch_bounds__(256) k_fillgemm(const int* __restrict__ ei32,
                                                  const float* __restrict__ x,
                                                  const float* __restrict__ w1a) {
    if (blockIdx.x < NB_EDGE) {
        int e = blockIdx.x * 256 + threadIdx.x;
        if (e >= NE) return;
        int s, d;
        if (g_is64) {
            s = ((const int2*)ei32)[e].x;                    // LDG.64, low word
            d = ((const int2*)ei32)[(size_t)NE + e].x;
        } else {
            s = ei32[e];
            d = ei32[NE + e];
        }
        int pos = atomicAdd(&g_deg[d], 1);
        if (pos < CAP) g_slot[(size_t)d * CAP + pos] = s;
        return;
    }

    // ---- gemm1 path ----
    __shared__ float4 ws[FIN * (DIM / 4)];            // 16 KB
    for (int i = threadIdx.x; i < FIN * DIM / 4; i += 256)
        ws[i] = ((const float4*)w1a)[i];
    __syncthreads();

    int n = (blockIdx.x - NB_EDGE) * 256 + threadIdx.x;
    if (n >= NN) return;

    u64 acc[DIM / 2];
#pragma unroll
    for (int j = 0; j < DIM / 2; j++) acc[j] = 0ull;

    const float4* xr = (const float4*)(x + (size_t)n * FIN);
    for (int kk = 0; kk < FIN / 4; kk++) {
        float4 xv = xr[kk];
#pragma unroll
        for (int u = 0; u < 4; u++) {
            float xs = (u == 0) ? xv.x : (u == 1) ? xv.y : (u == 2) ? xv.z : xv.w;
            u64 xs2 = bcast2(xs);
            const ulonglong2* wr = (const ulonglong2*)&ws[(kk * 4 + u) * 8];
#pragma unroll
            for (int j4 = 0; j4 < 8; j4++) {
                ulonglong2 w = wr[j4];
                fma2(acc[2*j4],     xs2, w.x);
                fma2(acc[2*j4 + 1], xs2, w.y);
            }
        }
    }
    u64* yr = (u64*)(g_y + (size_t)n * DIM);
#pragma unroll
    for (int j2 = 0; j2 < 16; j2++) yr[j2] = acc[j2];
}

// ---------------- gather-sum: warp per node, 4 neighbor-groups x 8 float4 lanes ----------------
template <int PASS>
__global__ void __launch_bounds__(256) k_gather() {
    int warp = (blockIdx.x * 256 + threadIdx.x) >> 5;
    int lane = threadIdx.x & 31;
    if (warp >= NN) return;

    const float* feat = (PASS == 0) ? g_y    : g_z;
    float*       agg  = (PASS == 0) ? g_aggY : g_aggZ;

    int grp = lane >> 3;          // neighbor group 0..3
    int col = lane & 7;           // float4 column 0..7

    const int* bucket = &g_slot[(size_t)warp * CAP];
    int cnt = g_deg[warp];
    if (cnt > CAP) cnt = CAP;

    float4 acc = make_float4(0.f, 0.f, 0.f, 0.f);
#pragma unroll 2
    for (int p = 0; p < cnt; p += 4) {
        int nb = p + grp;
        if (nb < cnt) {
            int s = __ldg(&bucket[nb]);                        // 8-lane broadcast
            float4 v = __ldg((const float4*)(feat + (size_t)s * DIM) + col);
            acc.x += v.x; acc.y += v.y; acc.z += v.z; acc.w += v.w;
        }
    }
#pragma unroll
    for (int off = 16; off >= 8; off >>= 1) {
        acc.x += __shfl_xor_sync(0xffffffffu, acc.x, off);
        acc.y += __shfl_xor_sync(0xffffffffu, acc.y, off);
        acc.z += __shfl_xor_sync(0xffffffffu, acc.z, off);
        acc.w += __shfl_xor_sync(0xffffffffu, acc.w, off);
    }
    if (grp == 0)
        ((float4*)(agg + (size_t)warp * DIM))[col] = acc;
}

// ---------------- K3: 1 node/thread, activations staged in smem -> low regs, high occ ----------------
__global__ void __launch_bounds__(256, 4) k_mlp1(const float* __restrict__ b1a,
                                                 const float* __restrict__ w1b,
                                                 const float* __restrict__ b1b) {
    __shared__ float4 w1b_s[DIM * 8];                 // 4 KB
    __shared__ float4 w2a_s[DIM * 8];                 // 4 KB
    __shared__ float b1a_s[DIM], b1b_s[DIM], c2a_s[DIM];
    __shared__ float sbuf[256 * SAS];                 // 33.8 KB (thread-private slots)
    int t = threadIdx.x;
    for (int i = t; i < DIM * 8; i += 256) {
        w1b_s[i] = ((const float4*)w1b)[i];
        w2a_s[i] = ((const float4*)g_W2a)[i];
    }
    if (t < DIM) { b1a_s[t] = b1a[t]; b1b_s[t] = b1b[t]; c2a_s[t] = g_c2a[t]; }
    __syncthreads();

    int n = blockIdx.x * 256 + t;
    if (n >= NN) return;
    float* sl = &sbuf[t * SAS];                       // private slot, no syncs needed

    // stage tin = relu(agg + y + b1a) into smem
    {
        const float4* ay = (const float4*)(g_aggY + (size_t)n * DIM);
        const float4* yy = (const float4*)(g_y    + (size_t)n * DIM);
#pragma unroll
        for (int i = 0; i < 8; i++) {
            float4 a = ay[i], b = yy[i];
            sl[i*4+0] = fmaxf(a.x + b.x + b1a_s[i*4+0], 0.f);
            sl[i*4+1] = fmaxf(a.y + b.y + b1a_s[i*4+1], 0.f);
            sl[i*4+2] = fmaxf(a.z + b.z + b1a_s[i*4+2], 0.f);
            sl[i*4+3] = fmaxf(a.w + b.w + b1a_s[i*4+3], 0.f);
        }
    }

    // GEMV1: h = tin @ w1b + b1b
    {
        u64 h[16];
#pragma unroll
        for (int j = 0; j < 16; j++) h[j] = pk2(b1b_s[2*j], b1b_s[2*j+1]);
#pragma unroll
        for (int k = 0; k < DIM; k++) {
            u64 tk2 = bcast2(sl[k]);
            const ulonglong2* wr = (const ulonglong2*)&w1b_s[k * 8];
#pragma unroll
            for (int j4 = 0; j4 < 8; j4++) {
                ulonglong2 w = wr[j4];
                fma2(h[2*j4],     tk2, w.x);
                fma2(h[2*j4 + 1], tk2, w.y);
            }
        }
        // hr = relu(h) back into the slot (all reads of tin are done)
#pragma unroll
        for (int j = 0; j < 16; j++) {
            float2 f = up2(h[j]);
            sl[2*j]   = fmaxf(f.x, 0.f);
            sl[2*j+1] = fmaxf(f.y, 0.f);
        }
    }

    // GEMV2: z = hr @ W2a' + c2a -> global
    {
        u64 z[16];
#pragma unroll
        for (int j = 0; j < 16; j++) z[j] = pk2(c2a_s[2*j], c2a_s[2*j+1]);
#pragma unroll
        for (int k = 0; k < DIM; k++) {
            u64 rk2 = bcast2(sl[k]);
            const ulonglong2* wr = (const ulonglong2*)&w2a_s[k * 8];
#pragma unroll
            for (int j4 = 0; j4 < 8; j4++) {
                ulonglong2 w = wr[j4];
                fma2(z[2*j4],     rk2, w.x);
                fma2(z[2*j4 + 1], rk2, w.y);
            }
        }
        u64* zr = (u64*)(g_z + (size_t)n * DIM);
#pragma unroll
        for (int j = 0; j < 16; j++) zr[j] = z[j];
    }
}

// ---------------- K5: 1 node/thread epilogue + log_softmax, smem-staged ----------------
__global__ void __launch_bounds__(256, 3) k_final(const float* __restrict__ b2a,
                                                  const float* __restrict__ fc1_w,
                                                  const float* __restrict__ fc1_b,
                                                  const float* __restrict__ fc2_w,
                                                  const float* __restrict__ fc2_b,
                                                  float* __restrict__ out) {
    __shared__ float4 w2b_s[DIM * 8];
    __shared__ float4 fc1_s[DIM * 8];
    __shared__ float4 fc2_s[DIM * NC / 4];            // 5 KB
    __shared__ float b2a_s[DIM], bb2_s[DIM], fc1b_s[DIM], fc2b_s[NC];
    __shared__ float sbuf[256 * SAS];                 // 33.8 KB (total ~47.5 KB)
    int t = threadIdx.x;
    for (int i = t; i < DIM * 8; i += 256) {
        w2b_s[i] = ((const float4*)g_W2b)[i];
        fc1_s[i] = ((const float4*)fc1_w)[i];
    }
    for (int i = t; i < DIM * NC / 4; i += 256)
        fc2_s[i] = ((const float4*)fc2_w)[i];
    if (t < DIM) { b2a_s[t] = b2a[t]; bb2_s[t] = g_bb2[t]; fc1b_s[t] = fc1_b[t]; }
    if (t < NC)  fc2b_s[t] = fc2_b[t];
    __syncthreads();

    int n = blockIdx.x * 256 + t;
    if (n >= NN) return;
    float* sl = &sbuf[t * SAS];

    // stage q = relu(aggZ + z + b2a)
    {
        const float4* az = (const float4*)(g_aggZ + (size_t)n * DIM);
        const float4* zz = (const float4*)(g_z    + (size_t)n * DIM);
#pragma unroll
        for (int i = 0; i < 8; i++) {
            float4 a = az[i], b = zz[i];
            sl[i*4+0] = fmaxf(a.x + b.x + b2a_s[i*4+0], 0.f);
            sl[i*4+1] = fmaxf(a.y + b.y + b2a_s[i*4+1], 0.f);
            sl[i*4+2] = fmaxf(a.z + b.z + b2a_s[i*4+2], 0.f);
            sl[i*4+3] = fmaxf(a.w + b.w + b2a_s[i*4+3], 0.f);
        }
    }

    // u = q @ W2b' + b2b' (no relu)
    {
        u64 u[16];
#pragma unroll
        for (int j = 0; j < 16; j++) u[j] = pk2(bb2_s[2*j], bb2_s[2*j+1]);
#pragma unroll
        for (int k = 0; k < DIM; k++) {
            u64 qk2 = bcast2(sl[k]);
            const ulonglong2* wr = (const ulonglong2*)&w2b_s[k * 8];
#pragma unroll
            for (int j4 = 0; j4 < 8; j4++) {
                ulonglong2 w = wr[j4];
                fma2(u[2*j4],     qk2, w.x);
                fma2(u[2*j4 + 1], qk2, w.y);
            }
        }
#pragma unroll
        for (int j = 0; j < 16; j++) {
            float2 f = up2(u[j]);
            sl[2*j] = f.x; sl[2*j+1] = f.y;
        }
    }

    // r = relu(u @ fc1_w + fc1_b)
    {
        u64 r[16];
#pragma unroll
        for (int j = 0; j < 16; j++) r[j] = pk2(fc1b_s[2*j], fc1b_s[2*j+1]);
#pragma unroll
        for (int k = 0; k < DIM; k++) {
            u64 uk2 = bcast2(sl[k]);
            const ulonglong2* wr = (const ulonglong2*)&fc1_s[k * 8];
#pragma unroll
            for (int j4 = 0; j4 < 8; j4++) {
                ulonglong2 w = wr[j4];
                fma2(r[2*j4],     uk2, w.x);
                fma2(r[2*j4 + 1], uk2, w.y);
            }
        }
#pragma unroll
        for (int j = 0; j < 16; j++) {
            float2 f = up2(r[j]);
            sl[2*j]   = fmaxf(f.x, 0.f);
            sl[2*j+1] = fmaxf(f.y, 0.f);
        }
    }

    // logits = r @ fc2_w + fc2_b (32 x 40) + log_softmax
    {
        u64 l[NC / 2];
#pragma unroll
        for (int c = 0; c < NC / 2; c++) l[c] = pk2(fc2b_s[2*c], fc2b_s[2*c+1]);
#pragma unroll
        for (int k = 0; k < DIM; k++) {
            u64 rk2 = bcast2(sl[k]);
            const ulonglong2* wr = (const ulonglong2*)&fc2_s[k * (NC / 4)];
#pragma unroll
            for (int c2 = 0; c2 < NC / 4; c2++) {    // 10 ulonglong2 per row
                ulonglong2 w = wr[c2];
                fma2(l[2*c2],     rk2, w.x);
                fma2(l[2*c2 + 1], rk2, w.y);
            }
        }
        float lf[NC];
#pragma unroll
        for (int c2 = 0; c2 < NC / 2; c2++) {
            float2 f = up2(l[c2]);
            lf[2*c2] = f.x; lf[2*c2+1] = f.y;
        }

        float m = lf[0];
#pragma unroll
        for (int c = 1; c < NC; c++) m = fmaxf(m, lf[c]);
        float ssum = 0.f;
#pragma unroll
        for (int c = 0; c < NC; c++) ssum += expf(lf[c] - m);
        float lse = m + logf(ssum);

        float4* orow = (float4*)(out + (size_t)n * NC);
#pragma unroll
        for (int c4 = 0; c4 < NC / 4; c4++)
            orow[c4] = make_float4(lf[c4*4+0]-lse, lf[c4*4+1]-lse,
                                   lf[c4*4+2]-lse, lf[c4*4+3]-lse);
    }
}

// ---------------- launch ----------------
extern "C" void kernel_launch(void* const* d_in, const int* in_sizes, int n_in,
                              void* d_out, int out_size) {
    const float* x     = (const float*)d_in[0];
    const int*   ei32  = (const int*)d_in[1];       // int32 OR int64 (detected on device)
    const float* w1a   = (const float*)d_in[2];
    const float* b1a   = (const float*)d_in[3];
    const float* w1b   = (const float*)d_in[4];
    const float* b1b   = (const float*)d_in[5];
    const float* w2a   = (const float*)d_in[6];
    const float* b2a   = (const float*)d_in[7];
    const float* w2b   = (const float*)d_in[8];
    const float* b2b   = (const float*)d_in[9];
    const float* bn1_g = (const float*)d_in[10];
    const float* bn1_b = (const float*)d_in[11];
    const float* bn1_m = (const float*)d_in[12];
    const float* bn1_v = (const float*)d_in[13];
    const float* bn2_g = (const float*)d_in[14];
    const float* bn2_b = (const float*)d_in[15];
    const float* bn2_m = (const float*)d_in[16];
    const float* bn2_v = (const float*)d_in[17];
    const float* fc1_w = (const float*)d_in[18];
    const float* fc1_b = (const float*)d_in[19];
    const float* fc2_w = (const float*)d_in[20];
    const float* fc2_b = (const float*)d_in[21];
    float* out = (float*)d_out;

    const int NB_WARP = (NN * 32 + 255) / 256;      // 12500, warp per node
    const int NB_INIT = 1 + (NN + 1023) / 1024;     // 99

    // 6 launches; profiled (4th) launch is k_mlp1 (verifying occ/issue prediction)
    k_initsetup<<<NB_INIT, 1024>>>(ei32, w2a, bn1_g, bn1_b, bn1_m, bn1_v,
                                   w2b, b2b, bn2_g, bn2_b, bn2_m, bn2_v);
    k_fillgemm<<<NB_EDGE + NB_NODE, 256>>>(ei32, x, w1a);
    k_gather<0><<<NB_WARP, 256>>>();
    k_mlp1<<<NB_NODE, 256>>>(b1a, w1b, b1b);
    k_gather<1><<<NB_WARP, 256>>>();
    k_final<<<NB_NODE, 256>>>(b2a, fc1_w, fc1_b, fc2_w, fc2_b, out);
}

// round 17
// speedup vs baseline: 1.0549x; 1.0549x over previous
#include <cuda_runtime.h>

#define NN   100000
#define NE   1600000
#define FIN  128
#define DIM  32
#define NC   40
#define CAP  128          // per-node bucket capacity (Poisson(16) -> P(>128) ~ 1e-80)
#define SAS  33           // smem activation stride: bank (nl+k)%32 -> conflict-free

#define NB_EDGE ((NE + 255) / 256)     // 6250
#define NB_NODE ((NN + 255) / 256)     // 391
#define NB_PAIR ((NN + 127) / 128)     // 782: 128 nodes per 256-thread block (2 thr/node)

// ---------------- scratch (device globals — no runtime alloc) ----------------
__device__ __align__(16) float g_y   [(size_t)NN * DIM];
__device__ __align__(16) float g_aggY[(size_t)NN * DIM];
__device__ __align__(16) float g_z   [(size_t)NN * DIM];
__device__ __align__(16) float g_aggZ[(size_t)NN * DIM];
__device__ __align__(16) int   g_slot[(size_t)NN * CAP];   // bucketed CSC
__device__ __align__(16) int   g_deg [NN];
__device__ int g_is64;
__device__ __align__(16) float g_W2a [DIM * DIM];   // diag(s1) @ w2a
__device__ __align__(16) float g_c2a [DIM];         // (bn1_b - bn1_m*s1) @ w2a
__device__ __align__(16) float g_W2b [DIM * DIM];   // w2b @ diag(s2)
__device__ __align__(16) float g_bb2 [DIM];         // (b2b - bn2_m)*s2 + bn2_b

// ---------------- f32x2 packed-FMA helpers ----------------
typedef unsigned long long u64;
__device__ __forceinline__ void fma2(u64& d, u64 a, u64 b) {
    asm("fma.rn.f32x2 %0, %1, %2, %0;" : "+l"(d) : "l"(a), "l"(b));
}
__device__ __forceinline__ u64 bcast2(float a) {
    u64 v; asm("mov.b64 %0, {%1, %1};" : "=l"(v) : "f"(a)); return v;
}
__device__ __forceinline__ u64 pk2(float a, float b) {
    u64 v; asm("mov.b64 %0, {%1, %2};" : "=l"(v) : "f"(a), "f"(b)); return v;
}
__device__ __forceinline__ float2 up2(u64 v) {
    float2 f; asm("mov.b64 {%0, %1}, %2;" : "=f"(f.x), "=f"(f.y) : "l"(v)); return f;
}

// ---------------- init+setup: detect dtype, zero deg, fold BN (one launch) ----------------
__global__ void __launch_bounds__(1024) k_initsetup(
    const int* __restrict__ ei32,
    const float* __restrict__ w2a,
    const float* __restrict__ bn1_g, const float* __restrict__ bn1_b,
    const float* __restrict__ bn1_m, const float* __restrict__ bn1_v,
    const float* __restrict__ w2b,  const float* __restrict__ b2b,
    const float* __restrict__ bn2_g, const float* __restrict__ bn2_b,
    const float* __restrict__ bn2_m, const float* __restrict__ bn2_v) {
    int tid = threadIdx.x;
    if (blockIdx.x == 0) {
        if (tid == 0) {
            int all_zero = 1;
            for (int q = 1; q < 128; q += 2)
                if (ei32[q] != 0) { all_zero = 0; break; }
            g_is64 = all_zero;
        }
        int k = tid >> 5, j = tid & 31;
        float s1k = bn1_g[k] * rsqrtf(bn1_v[k] + 1e-5f);
        g_W2a[tid] = s1k * w2a[tid];
        float s2j = bn2_g[j] * rsqrtf(bn2_v[j] + 1e-5f);
        g_W2b[tid] = w2b[tid] * s2j;
        if (tid < DIM) {
            float c = 0.f;
            for (int kk = 0; kk < DIM; kk++) {
                float s = bn1_g[kk] * rsqrtf(bn1_v[kk] + 1e-5f);
                c += (bn1_b[kk] - bn1_m[kk] * s) * w2a[kk * DIM + tid];
            }
            g_c2a[tid] = c;
            float s2 = bn2_g[tid] * rsqrtf(bn2_v[tid] + 1e-5f);
            g_bb2[tid] = (b2b[tid] - bn2_m[tid]) * s2 + bn2_b[tid];
        }
    } else {
        int i = (blockIdx.x - 1) * 1024 + tid;
        if (i < NN) g_deg[i] = 0;
    }
}

// ---------------- fused: CSC fill (blocks [0,NB_EDGE)) + gemm1 (rest) ----------------
__global__ void __launch_bounds__(256) k_fillgemm(const int* __restrict__ ei32,
                                                  const float* __restrict__ x,
                                                  const float* __restrict__ w1a) {
    if (blockIdx.x < NB_EDGE) {
        int e = blockIdx.x * 256 + threadIdx.x;
        if (e >= NE) return;
        int s, d;
        if (g_is64) {
            s = ((const int2*)ei32)[e].x;                    // LDG.64, low word
            d = ((const int2*)ei32)[(size_t)NE + e].x;
        } else {
            s = ei32[e];
            d = ei32[NE + e];
        }
        int pos = atomicAdd(&g_deg[d], 1);
        if (pos < CAP) g_slot[(size_t)d * CAP + pos] = s;
        return;
    }

    // ---- gemm1 path ----
    __shared__ float4 ws[FIN * (DIM / 4)];            // 16 KB
    for (int i = threadIdx.x; i < FIN * DIM / 4; i += 256)
        ws[i] = ((const float4*)w1a)[i];
    __syncthreads();

    int n = (blockIdx.x - NB_EDGE) * 256 + threadIdx.x;
    if (n >= NN) return;

    u64 acc[DIM / 2];
#pragma unroll
    for (int j = 0; j < DIM / 2; j++) acc[j] = 0ull;

    const float4* xr = (const float4*)(x + (size_t)n * FIN);
    for (int kk = 0; kk < FIN / 4; kk++) {
        float4 xv = xr[kk];
#pragma unroll
        for (int u = 0; u < 4; u++) {
            float xs = (u == 0) ? xv.x : (u == 1) ? xv.y : (u == 2) ? xv.z : xv.w;
            u64 xs2 = bcast2(xs);
            const ulonglong2* wr = (const ulonglong2*)&ws[(kk * 4 + u) * 8];
#pragma unroll
            for (int j4 = 0; j4 < 8; j4++) {
                ulonglong2 w = wr[j4];
                fma2(acc[2*j4],     xs2, w.x);
                fma2(acc[2*j4 + 1], xs2, w.y);
            }
        }
    }
    u64* yr = (u64*)(g_y + (size_t)n * DIM);
#pragma unroll
    for (int j2 = 0; j2 < 16; j2++) yr[j2] = acc[j2];
}

// ---------------- gather-sum: warp per node, 4 neighbor-groups x 8 float4 lanes ----------------
template <int PASS>
__global__ void __launch_bounds__(256) k_gather() {
    int warp = (blockIdx.x * 256 + threadIdx.x) >> 5;
    int lane = threadIdx.x & 31;
    if (warp >= NN) return;

    const float* feat = (PASS == 0) ? g_y    : g_z;
    float*       agg  = (PASS == 0) ? g_aggY : g_aggZ;

    int grp = lane >> 3;          // neighbor group 0..3
    int col = lane & 7;           // float4 column 0..7

    const int* bucket = &g_slot[(size_t)warp * CAP];
    int cnt = g_deg[warp];
    if (cnt > CAP) cnt = CAP;

    float4 acc = make_float4(0.f, 0.f, 0.f, 0.f);
#pragma unroll 2
    for (int p = 0; p < cnt; p += 4) {
        int nb = p + grp;
        if (nb < cnt) {
            int s = __ldg(&bucket[nb]);                        // 8-lane broadcast
            float4 v = __ldg((const float4*)(feat + (size_t)s * DIM) + col);
            acc.x += v.x; acc.y += v.y; acc.z += v.z; acc.w += v.w;
        }
    }
#pragma unroll
    for (int off = 16; off >= 8; off >>= 1) {
        acc.x += __shfl_xor_sync(0xffffffffu, acc.x, off);
        acc.y += __shfl_xor_sync(0xffffffffu, acc.y, off);
        acc.z += __shfl_xor_sync(0xffffffffu, acc.z, off);
        acc.w += __shfl_xor_sync(0xffffffffu, acc.w, off);
    }
    if (grp == 0)
        ((float4*)(agg + (size_t)warp * DIM))[col] = acc;
}

// ---------------- K3: 2 threads/node — each computes 16 of 32 cols per GEMV ----------------
// 256 threads = 128 nodes/block. Pair (t, t^1) shares smem slot sbuf[nl*SAS];
// exchange via __syncwarp (partner is in the same warp). No early returns.
__global__ void __launch_bounds__(256) k_mlp1(const float* __restrict__ b1a,
                                              const float* __restrict__ w1b,
                                              const float* __restrict__ b1b) {
    __shared__ float4 w1b_s[DIM * 8];                 // 4 KB
    __shared__ float4 w2a_s[DIM * 8];                 // 4 KB
    __shared__ float b1a_s[DIM], b1b_s[DIM], c2a_s[DIM];
    __shared__ float sbuf[128 * SAS];                 // 16.9 KB
    int t = threadIdx.x;
    for (int i = t; i < DIM * 8; i += 256) {
        w1b_s[i] = ((const float4*)w1b)[i];
        w2a_s[i] = ((const float4*)g_W2a)[i];
    }
    if (t < DIM) { b1a_s[t] = b1a[t]; b1b_s[t] = b1b[t]; c2a_s[t] = g_c2a[t]; }
    __syncthreads();

    int nl = t >> 1, half = t & 1;
    int n = blockIdx.x * 128 + nl;
    bool valid = n < NN;
    size_t cn = valid ? (size_t)n : (size_t)(NN - 1);   // clamp loads, guard stores
    float* sl = &sbuf[nl * SAS];
    int hb = half * 16;                                  // column base of my half

    // stage my half of tin = relu(agg + y + b1a)
    {
        const float4* ay = (const float4*)(g_aggY + cn * DIM) + half * 4;
        const float4* yy = (const float4*)(g_y    + cn * DIM) + half * 4;
#pragma unroll
        for (int i = 0; i < 4; i++) {
            float4 a = ay[i], b = yy[i];
            int c = hb + i * 4;
            sl[c+0] = fmaxf(a.x + b.x + b1a_s[c+0], 0.f);
            sl[c+1] = fmaxf(a.y + b.y + b1a_s[c+1], 0.f);
            sl[c+2] = fmaxf(a.z + b.z + b1a_s[c+2], 0.f);
            sl[c+3] = fmaxf(a.w + b.w + b1a_s[c+3], 0.f);
        }
    }
    __syncwarp();

    // GEMV1 half: h[cols hb..hb+15] = tin @ w1b + b1b
    u64 h[8];
#pragma unroll
    for (int j = 0; j < 8; j++) h[j] = pk2(b1b_s[hb + 2*j], b1b_s[hb + 2*j + 1]);
#pragma unroll
    for (int k = 0; k < DIM; k++) {
        u64 tk2 = bcast2(sl[k]);
        const ulonglong2* wr = (const ulonglong2*)&w1b_s[k * 8] + half * 4;
#pragma unroll
        for (int j4 = 0; j4 < 4; j4++) {
            ulonglong2 w = wr[j4];
            fma2(h[2*j4],     tk2, w.x);
            fma2(h[2*j4 + 1], tk2, w.y);
        }
    }
    __syncwarp();                                       // partner done reading tin
#pragma unroll
    for (int j = 0; j < 8; j++) {
        float2 f = up2(h[j]);
        sl[hb + 2*j]     = fmaxf(f.x, 0.f);
        sl[hb + 2*j + 1] = fmaxf(f.y, 0.f);
    }
    __syncwarp();

    // GEMV2 half: z[cols hb..hb+15] = hr @ W2a' + c2a -> global
    u64 z[8];
#pragma unroll
    for (int j = 0; j < 8; j++) z[j] = pk2(c2a_s[hb + 2*j], c2a_s[hb + 2*j + 1]);
#pragma unroll
    for (int k = 0; k < DIM; k++) {
        u64 rk2 = bcast2(sl[k]);
        const ulonglong2* wr = (const ulonglong2*)&w2a_s[k * 8] + half * 4;
#pragma unroll
        for (int j4 = 0; j4 < 4; j4++) {
            ulonglong2 w = wr[j4];
            fma2(z[2*j4],     rk2, w.x);
            fma2(z[2*j4 + 1], rk2, w.y);
        }
    }
    if (valid) {
        u64* zr = (u64*)(g_z + (size_t)n * DIM) + half * 8;
#pragma unroll
        for (int j = 0; j < 8; j++) zr[j] = z[j];
    }
}

// ---------------- K5: 2 threads/node epilogue + pair-split log_softmax ----------------
__global__ void __launch_bounds__(256) k_final(const float* __restrict__ b2a,
                                               const float* __restrict__ fc1_w,
                                               const float* __restrict__ fc1_b,
                                               const float* __restrict__ fc2_w,
                                               const float* __restrict__ fc2_b,
                                               float* __restrict__ out) {
    __shared__ float4 w2b_s[DIM * 8];
    __shared__ float4 fc1_s[DIM * 8];
    __shared__ float4 fc2_s[DIM * NC / 4];            // 5 KB
    __shared__ float b2a_s[DIM], bb2_s[DIM], fc1b_s[DIM], fc2b_s[NC];
    __shared__ float sbuf[128 * SAS];                 // 16.9 KB
    int t = threadIdx.x;
    for (int i = t; i < DIM * 8; i += 256) {
        w2b_s[i] = ((const float4*)g_W2b)[i];
        fc1_s[i] = ((const float4*)fc1_w)[i];
    }
    for (int i = t; i < DIM * NC / 4; i += 256)
        fc2_s[i] = ((const float4*)fc2_w)[i];
    if (t < DIM) { b2a_s[t] = b2a[t]; bb2_s[t] = g_bb2[t]; fc1b_s[t] = fc1_b[t]; }
    if (t < NC)  fc2b_s[t] = fc2_b[t];
    __syncthreads();

    int nl = t >> 1, half = t & 1;
    int n = blockIdx.x * 128 + nl;
    bool valid = n < NN;
    size_t cn = valid ? (size_t)n : (size_t)(NN - 1);
    float* sl = &sbuf[nl * SAS];
    int hb = half * 16;

    // stage my half of q = relu(aggZ + z + b2a)
    {
        const float4* az = (const float4*)(g_aggZ + cn * DIM) + half * 4;
        const float4* zz = (const float4*)(g_z    + cn * DIM) + half * 4;
#pragma unroll
        for (int i = 0; i < 4; i++) {
            float4 a = az[i], b = zz[i];
            int c = hb + i * 4;
            sl[c+0] = fmaxf(a.x + b.x + b2a_s[c+0], 0.f);
            sl[c+1] = fmaxf(a.y + b.y + b2a_s[c+1], 0.f);
            sl[c+2] = fmaxf(a.z + b.z + b2a_s[c+2], 0.f);
            sl[c+3] = fmaxf(a.w + b.w + b2a_s[c+3], 0.f);
        }
    }
    __syncwarp();

    // u half = q @ W2b' + b2b' (no relu)
    {
        u64 u[8];
#pragma unroll
        for (int j = 0; j < 8; j++) u[j] = pk2(bb2_s[hb + 2*j], bb2_s[hb + 2*j + 1]);
#pragma unroll
        for (int k = 0; k < DIM; k++) {
            u64 qk2 = bcast2(sl[k]);
            const ulonglong2* wr = (const ulonglong2*)&w2b_s[k * 8] + half * 4;
#pragma unroll
            for (int j4 = 0; j4 < 4; j4++) {
                ulonglong2 w = wr[j4];
                fma2(u[2*j4],     qk2, w.x);
                fma2(u[2*j4 + 1], qk2, w.y);
            }
        }
        __syncwarp();                                   // partner done reading q
#pragma unroll
        for (int j = 0; j < 8; j++) {
            float2 f = up2(u[j]);
            sl[hb + 2*j] = f.x; sl[hb + 2*j + 1] = f.y;
        }
        __syncwarp();
    }

    // r half = relu(u @ fc1_w + fc1_b)
    {
        u64 r[8];
#pragma unroll
        for (int j = 0; j < 8; j++) r[j] = pk2(fc1b_s[hb + 2*j], fc1b_s[hb + 2*j + 1]);
#pragma unroll
        for (int k = 0; k < DIM; k++) {
            u64 uk2 = bcast2(sl[k]);
            const ulonglong2* wr = (const ulonglong2*)&fc1_s[k * 8] + half * 4;
#pragma unroll
            for (int j4 = 0; j4 < 4; j4++) {
                ulonglong2 w = wr[j4];
                fma2(r[2*j4],     uk2, w.x);
                fma2(r[2*j4 + 1], uk2, w.y);
            }
        }
        __syncwarp();                                   // partner done reading u
#pragma unroll
        for (int j = 0; j < 8; j++) {
            float2 f = up2(r[j]);
            sl[hb + 2*j]     = fmaxf(f.x, 0.f);
            sl[hb + 2*j + 1] = fmaxf(f.y, 0.f);
        }
        __syncwarp();
    }

    // logits half: cols [half*20, half*20+20) = r @ fc2_w + fc2_b
    u64 l[10];
    int cb = half * 20;
#pragma unroll
    for (int c = 0; c < 10; c++) l[c] = pk2(fc2b_s[cb + 2*c], fc2b_s[cb + 2*c + 1]);
#pragma unroll
    for (int k = 0; k < DIM; k++) {
        u64 rk2 = bcast2(sl[k]);
        const ulonglong2* wr = (const ulonglong2*)&fc2_s[k * (NC / 4)] + half * 5;
#pragma unroll
        for (int c2 = 0; c2 < 5; c2++) {
            ulonglong2 w = wr[c2];
            fma2(l[2*c2],     rk2, w.x);
            fma2(l[2*c2 + 1], rk2, w.y);
        }
    }
    float lf[20];
#pragma unroll
    for (int c2 = 0; c2 < 10; c2++) {
        float2 f = up2(l[c2]);
        lf[2*c2] = f.x; lf[2*c2 + 1] = f.y;
    }

    // pair-split log_softmax: combine max and expsum with partner via shfl_xor(1)
    float m = lf[0];
#pragma unroll
    for (int c = 1; c < 20; c++) m = fmaxf(m, lf[c]);
    m = fmaxf(m, __shfl_xor_sync(0xffffffffu, m, 1));
    float ssum = 0.f;
#pragma unroll
    for (int c = 0; c < 20; c++) ssum += expf(lf[c] - m);
    ssum += __shfl_xor_sync(0xffffffffu, ssum, 1);
    float lse = m + logf(ssum);

    if (valid) {
        float4* orow = (float4*)(out + (size_t)n * NC) + half * 5;
#pragma unroll
        for (int c4 = 0; c4 < 5; c4++)
            orow[c4] = make_float4(lf[c4*4+0]-lse, lf[c4*4+1]-lse,
                                   lf[c4*4+2]-lse, lf[c4*4+3]-lse);
    }
}

// ---------------- launch ----------------
extern "C" void kernel_launch(void* const* d_in, const int* in_sizes, int n_in,
                              void* d_out, int out_size) {
    const float* x     = (const float*)d_in[0];
    const int*   ei32  = (const int*)d_in[1];       // int32 OR int64 (detected on device)
    const float* w1a   = (const float*)d_in[2];
    const float* b1a   = (const float*)d_in[3];
    const float* w1b   = (const float*)d_in[4];
    const float* b1b   = (const float*)d_in[5];
    const float* w2a   = (const float*)d_in[6];
    const float* b2a   = (const float*)d_in[7];
    const float* w2b   = (const float*)d_in[8];
    const float* b2b   = (const float*)d_in[9];
    const float* bn1_g = (const float*)d_in[10];
    const float* bn1_b = (const float*)d_in[11];
    const float* bn1_m = (const float*)d_in[12];
    const float* bn1_v = (const float*)d_in[13];
    const float* bn2_g = (const float*)d_in[14];
    const float* bn2_b = (const float*)d_in[15];
    const float* bn2_m = (const float*)d_in[16];
    const float* bn2_v = (const float*)d_in[17];
    const float* fc1_w = (const float*)d_in[18];
    const float* fc1_b = (const float*)d_in[19];
    const float* fc2_w = (const float*)d_in[20];
    const float* fc2_b = (const float*)d_in[21];
    float* out = (float*)d_out;

    const int NB_WARP = (NN * 32 + 255) / 256;      // 12500, warp per node
    const int NB_INIT = 1 + (NN + 1023) / 1024;     // 99

    // 6 launches; profiled (4th) launch is k_mlp1 (verifying the 2-thread/node split)
    k_initsetup<<<NB_INIT, 1024>>>(ei32, w2a, bn1_g, bn1_b, bn1_m, bn1_v,
                                   w2b, b2b, bn2_g, bn2_b, bn2_m, bn2_v);
    k_fillgemm<<<NB_EDGE + NB_NODE, 256>>>(ei32, x, w1a);
    k_gather<0><<<NB_WARP, 256>>>();
    k_mlp1<<<NB_PAIR, 256>>>(b1a, w1b, b1b);
    k_gather<1><<<NB_WARP, 256>>>();
    k_final<<<NB_PAIR, 256>>>(b2a, fc1_w, fc1_b, fc2_w, fc2_b, out);
}